// round 2
// baseline (speedup 1.0000x reference)
#include <cuda_runtime.h>
#include <math.h>

#define B_   4
#define L_   2048
#define D_   512
#define S_   256
#define NL_  6
#define H_   8
#define DH_  64
#define WIN_ 256

// ---------------- scratch (device globals; no allocation) ----------------
__device__ float g_X[B_*L_*D_];        // conv+silu output / proj scratch
__device__ float g_U[B_*L_*S_];        // mamba u
__device__ float g_QKV[B_*L_*3*D_];    // qkv
__device__ float g_ATT[B_*L_*D_];      // attention context
__device__ float g_HT[B_*S_];          // final ssm state
__device__ float g_STATE[B_*D_];       // per-layer state summary

// ---------------- zero state ----------------
__global__ void zero_state_kernel() {
    int t = blockIdx.x * blockDim.x + threadIdx.x;
    if (t < B_ * D_) g_STATE[t] = 0.f;
}

// ---------------- conv (k=3, causal) + SiLU ----------------
__global__ void conv_silu_kernel(const float* __restrict__ seq,
                                 const float* __restrict__ cw) {
    int row = blockIdx.x;            // b*L + l
    int l = row & (L_ - 1);
    int t = threadIdx.x;             // 128 threads, float4 each
    float4 z = make_float4(0.f, 0.f, 0.f, 0.f);
    float4 a0 = (l >= 2) ? ((const float4*)(seq + (size_t)(row - 2) * D_))[t] : z;
    float4 a1 = (l >= 1) ? ((const float4*)(seq + (size_t)(row - 1) * D_))[t] : z;
    float4 a2 = ((const float4*)(seq + (size_t)row * D_))[t];
    float4 w0 = ((const float4*)(cw        ))[t];
    float4 w1 = ((const float4*)(cw +   D_ ))[t];
    float4 w2 = ((const float4*)(cw + 2*D_ ))[t];
    float4 x;
    x.x = w0.x*a0.x + w1.x*a1.x + w2.x*a2.x;
    x.y = w0.y*a0.y + w1.y*a1.y + w2.y*a2.y;
    x.z = w0.z*a0.z + w1.z*a1.z + w2.z*a2.z;
    x.w = w0.w*a0.w + w1.w*a1.w + w2.w*a2.w;
    x.x = x.x / (1.f + __expf(-x.x));
    x.y = x.y / (1.f + __expf(-x.y));
    x.z = x.z / (1.f + __expf(-x.z));
    x.w = x.w / (1.f + __expf(-x.w));
    ((float4*)(g_X + (size_t)row * D_))[t] = x;
}

// ---------------- generic tiled fp32 GEMM: C[M,N] = A[M,K] * B (+bias) ----
// TB=0: B is [K,N] row-major.  TB=1: B is [N,K] row-major (B transposed).
template <int TB>
__global__ void gemm_kernel(const float* __restrict__ A, const float* __restrict__ B,
                            const float* __restrict__ bias, float* __restrict__ C,
                            int M, int N, int K) {
    __shared__ float As[16][65];   // [k][m]
    __shared__ float Bs[16][65];   // [k][n]
    int bm = blockIdx.y * 64, bn = blockIdx.x * 64;
    int tid = threadIdx.x;
    int ty = tid >> 4, tx = tid & 15;
    float acc[4][4];
#pragma unroll
    for (int i = 0; i < 4; i++)
#pragma unroll
        for (int j = 0; j < 4; j++) acc[i][j] = 0.f;

    for (int k0 = 0; k0 < K; k0 += 16) {
#pragma unroll
        for (int j = 0; j < 4; j++) {
            int idx = tid + 256 * j;
            int r = idx >> 4, c = idx & 15;
            As[c][r] = A[(size_t)(bm + r) * K + k0 + c];
        }
        if (TB == 0) {
#pragma unroll
            for (int j = 0; j < 4; j++) {
                int idx = tid + 256 * j;
                int kk = idx >> 6, n = idx & 63;
                Bs[kk][n] = B[(size_t)(k0 + kk) * N + bn + n];
            }
        } else {
#pragma unroll
            for (int j = 0; j < 4; j++) {
                int idx = tid + 256 * j;
                int r = idx >> 4, c = idx & 15;
                Bs[c][r] = B[(size_t)(bn + r) * K + k0 + c];
            }
        }
        __syncthreads();
#pragma unroll
        for (int kk = 0; kk < 16; kk++) {
            float av[4], bv[4];
#pragma unroll
            for (int i = 0; i < 4; i++) av[i] = As[kk][ty + 16 * i];
#pragma unroll
            for (int j = 0; j < 4; j++) bv[j] = Bs[kk][tx + 16 * j];
#pragma unroll
            for (int i = 0; i < 4; i++)
#pragma unroll
                for (int j = 0; j < 4; j++) acc[i][j] += av[i] * bv[j];
        }
        __syncthreads();
    }
#pragma unroll
    for (int i = 0; i < 4; i++) {
        int r = bm + ty + 16 * i;
#pragma unroll
        for (int j = 0; j < 4; j++) {
            int c = bn + tx + 16 * j;
            float v = acc[i][j];
            if (bias) v += bias[c];
            C[(size_t)r * N + c] = v;
        }
    }
}

// ---------------- hT[b,s] = a^L * (state@Wh)[b,s] + sum_l u * a^(L-1-l) ----
__global__ void ht_kernel(const float* __restrict__ Aparam,
                          const float* __restrict__ Wh) {
    __shared__ float sh[128], sh2[128];
    int bs = blockIdx.x;
    int b = bs >> 8, s = bs & 255;
    int t = threadIdx.x;   // 128
    float a = 1.f / (1.f + expf(-Aparam[s]));
    float h0p = 0.f;
#pragma unroll
    for (int j = 0; j < 4; j++) {
        int d = t + 128 * j;
        h0p += g_STATE[b * D_ + d] * Wh[(size_t)d * S_ + s];
    }
    const float* u = g_U + (size_t)b * L_ * S_ + s;
    float p = 0.f;
    int l0 = t * 16;
#pragma unroll
    for (int j = 0; j < 16; j++) p = p * a + u[(size_t)(l0 + j) * S_];
    float w = powf(a, (float)(L_ - 16 * (t + 1)));
    sh[t] = p * w;
    sh2[t] = h0p;
    __syncthreads();
    for (int st = 64; st; st >>= 1) {
        if (t < st) { sh[t] += sh[t + st]; sh2[t] += sh2[t + st]; }
        __syncthreads();
    }
    if (t == 0) g_HT[bs] = powf(a, (float)L_) * sh2[0] + sh[0];
}

// ---------------- state[b,d] = hT[b,:] @ Wout[:,d] ----------------
__global__ void stateout_kernel(const float* __restrict__ Wout) {
    __shared__ float ht[S_];
    int b = blockIdx.x;
    int d = threadIdx.x;   // 512
    if (d < S_) ht[d] = g_HT[b * S_ + d];
    __syncthreads();
    float acc = 0.f;
#pragma unroll 8
    for (int s = 0; s < S_; s++) acc += ht[s] * Wout[(size_t)s * D_ + d];
    g_STATE[b * D_ + d] = acc;
}

// ---------------- residual + LayerNorm ----------------
// bcast=1: add g_STATE[b,:] (broadcast over l).  bcast=0: add `add` row-wise.
__global__ void ln_kernel(const float* __restrict__ seq, const float* __restrict__ add,
                          const float* __restrict__ gamma, const float* __restrict__ beta,
                          float* __restrict__ out, int bcast) {
    __shared__ float red[4];
    __shared__ float stat;
    int row = blockIdx.x;
    int b = row >> 11;
    int t = threadIdx.x;   // 128
    float4 x = ((const float4*)(seq + (size_t)row * D_))[t];
    const float* ap = bcast ? (g_STATE + (size_t)b * D_) : (add + (size_t)row * D_);
    float4 a4 = ((const float4*)ap)[t];
    x.x += a4.x; x.y += a4.y; x.z += a4.z; x.w += a4.w;

    float sum = x.x + x.y + x.z + x.w;
    for (int off = 16; off; off >>= 1) sum += __shfl_xor_sync(0xffffffffu, sum, off);
    if ((t & 31) == 0) red[t >> 5] = sum;
    __syncthreads();
    if (t == 0) stat = (red[0] + red[1] + red[2] + red[3]) * (1.f / D_);
    __syncthreads();
    float mu = stat;
    float d0 = x.x - mu, d1 = x.y - mu, d2 = x.z - mu, d3 = x.w - mu;
    float sq = d0*d0 + d1*d1 + d2*d2 + d3*d3;
    for (int off = 16; off; off >>= 1) sq += __shfl_xor_sync(0xffffffffu, sq, off);
    if ((t & 31) == 0) red[t >> 5] = sq;
    __syncthreads();
    if (t == 0) stat = rsqrtf((red[0] + red[1] + red[2] + red[3]) * (1.f / D_) + 1e-5f);
    __syncthreads();
    float rs = stat;
    float4 g = ((const float4*)gamma)[t], be = ((const float4*)beta)[t];
    float4 y;
    y.x = d0 * rs * g.x + be.x;
    y.y = d1 * rs * g.y + be.y;
    y.z = d2 * rs * g.z + be.z;
    y.w = d3 * rs * g.w + be.w;
    ((float4*)(out + (size_t)row * D_))[t] = y;
}

// ---------------- banded flash attention ----------------
// block = (qt, h, b): 64 queries, key tiles of 32 over [q0-WIN, q0+63+WIN]
__global__ void attn_kernel() {
    __shared__ float Qt[64][65];   // [dim][q]
    __shared__ float Kt[64][33];   // [dim][k]
    __shared__ float Vs[32][65];   // [k][dim]
    __shared__ float Ps[64][33];   // [q][k]
    int b = blockIdx.z, h = blockIdx.y, qt = blockIdx.x;
    int q0 = qt * 64;
    int tid = threadIdx.x;
    int ty = tid >> 4, tx = tid & 15;

#pragma unroll
    for (int j = 0; j < 16; j++) {
        int idx = tid + 256 * j;
        int q = idx >> 6, dm = idx & 63;
        Qt[dm][q] = g_QKV[(size_t)(b * L_ + q0 + q) * (3 * D_) + h * DH_ + dm];
    }

    float m[4], lsum[4], o[4][4];
#pragma unroll
    for (int i = 0; i < 4; i++) {
        m[i] = -1e30f; lsum[i] = 0.f;
#pragma unroll
        for (int j = 0; j < 4; j++) o[i][j] = 0.f;
    }

    int kstart = q0 - WIN_; if (kstart < 0) kstart = 0;
    int kend = q0 + 64 + WIN_; if (kend > L_) kend = L_;

    for (int k0 = kstart; k0 < kend; k0 += 32) {
        __syncthreads();   // protect Kt/Vs/Ps (and first-pass Qt) before overwrite
#pragma unroll
        for (int j = 0; j < 8; j++) {
            int idx = tid + 256 * j;
            int kk = idx >> 6, dm = idx & 63;
            size_t base = (size_t)(b * L_ + k0 + kk) * (3 * D_) + h * DH_ + dm;
            Kt[dm][kk] = g_QKV[base + D_];
            Vs[kk][dm] = g_QKV[base + 2 * D_];
        }
        __syncthreads();

        float sc[4][2];
#pragma unroll
        for (int i = 0; i < 4; i++)
#pragma unroll
            for (int j = 0; j < 2; j++) sc[i][j] = 0.f;
#pragma unroll
        for (int kk = 0; kk < 64; kk++) {
            float av[4], bv[2];
#pragma unroll
            for (int i = 0; i < 4; i++) av[i] = Qt[kk][ty + 16 * i];
#pragma unroll
            for (int j = 0; j < 2; j++) bv[j] = Kt[kk][tx + 16 * j];
#pragma unroll
            for (int i = 0; i < 4; i++)
#pragma unroll
                for (int j = 0; j < 2; j++) sc[i][j] += av[i] * bv[j];
        }

#pragma unroll
        for (int i = 0; i < 4; i++) {
            int q = q0 + ty + 16 * i;
            float mx = -1e30f;
#pragma unroll
            for (int j = 0; j < 2; j++) {
                int k = k0 + tx + 16 * j;
                int dlt = q - k; if (dlt < 0) dlt = -dlt;
                sc[i][j] = (dlt <= WIN_) ? sc[i][j] * 0.125f : -1e30f;
                mx = fmaxf(mx, sc[i][j]);
            }
            for (int off = 8; off; off >>= 1)
                mx = fmaxf(mx, __shfl_xor_sync(0xffffffffu, mx, off));
            float mn = fmaxf(m[i], mx);
            float corr = __expf(m[i] - mn);
            float rs = 0.f;
#pragma unroll
            for (int j = 0; j < 2; j++) {
                float p = (sc[i][j] > -1e29f) ? __expf(sc[i][j] - mn) : 0.f;
                Ps[ty + 16 * i][tx + 16 * j] = p;
                rs += p;
            }
            for (int off = 8; off; off >>= 1)
                rs += __shfl_xor_sync(0xffffffffu, rs, off);
            lsum[i] = lsum[i] * corr + rs;
            m[i] = mn;
#pragma unroll
            for (int j = 0; j < 4; j++) o[i][j] *= corr;
        }
        __syncthreads();

#pragma unroll
        for (int kk = 0; kk < 32; kk++) {
            float pv[4], vv[4];
#pragma unroll
            for (int i = 0; i < 4; i++) pv[i] = Ps[ty + 16 * i][kk];
#pragma unroll
            for (int j = 0; j < 4; j++) vv[j] = Vs[kk][tx + 16 * j];
#pragma unroll
            for (int i = 0; i < 4; i++)
#pragma unroll
                for (int j = 0; j < 4; j++) o[i][j] += pv[i] * vv[j];
        }
    }

#pragma unroll
    for (int i = 0; i < 4; i++) {
        float inv = 1.f / lsum[i];
        int q = q0 + ty + 16 * i;
#pragma unroll
        for (int j = 0; j < 4; j++)
            g_ATT[(size_t)(b * L_ + q) * D_ + h * DH_ + tx + 16 * j] = o[i][j] * inv;
    }
}

// ---------------- launcher ----------------
extern "C" void kernel_launch(void* const* d_in, const int* in_sizes, int n_in,
                              void* d_out, int out_size) {
    const float* context = (const float*)d_in[0];
    const float* conv_w  = (const float*)d_in[1];
    const float* Wx      = (const float*)d_in[2];
    const float* Wh      = (const float*)d_in[3];
    const float* Wout    = (const float*)d_in[4];
    const float* Aparam  = (const float*)d_in[5];
    const float* gm      = (const float*)d_in[6];
    const float* bm      = (const float*)d_in[7];
    const float* ga      = (const float*)d_in[8];
    const float* ba      = (const float*)d_in[9];
    const float* Wqkv    = (const float*)d_in[10];
    const float* bqkv    = (const float*)d_in[11];
    const float* Wo      = (const float*)d_in[12];
    const float* bo      = (const float*)d_in[13];
    float* out = (float*)d_out;

    static void *pX = nullptr, *pU = nullptr, *pQKV = nullptr, *pATT = nullptr;
    if (!pX) {
        cudaGetSymbolAddress(&pX, g_X);
        cudaGetSymbolAddress(&pU, g_U);
        cudaGetSymbolAddress(&pQKV, g_QKV);
        cudaGetSymbolAddress(&pATT, g_ATT);
    }

    zero_state_kernel<<<(B_ * D_ + 255) / 256, 256>>>();

    for (int i = 0; i < NL_; i++) {
        const float* seqin = (i == 0) ? context : out;
        conv_silu_kernel<<<B_ * L_, 128>>>(seqin, conv_w + (size_t)i * 3 * D_);
        gemm_kernel<0><<<dim3(S_ / 64, B_ * L_ / 64), 256>>>(
            (const float*)pX, Wx + (size_t)i * D_ * S_, nullptr, (float*)pU,
            B_ * L_, S_, D_);
        ht_kernel<<<B_ * S_, 128>>>(Aparam + (size_t)i * S_, Wh + (size_t)i * D_ * S_);
        stateout_kernel<<<B_, D_>>>(Wout + (size_t)i * S_ * D_);
        ln_kernel<<<B_ * L_, 128>>>(seqin, nullptr, gm, bm, out, 1);

        if (((i + 1) % 4) == 0) {
            gemm_kernel<1><<<dim3(3 * D_ / 64, B_ * L_ / 64), 256>>>(
                out, Wqkv, bqkv, (float*)pQKV, B_ * L_, 3 * D_, D_);
            attn_kernel<<<dim3(L_ / 64, H_, B_), 256>>>();
            gemm_kernel<1><<<dim3(D_ / 64, B_ * L_ / 64), 256>>>(
                (const float*)pATT, Wo, bo, (float*)pX, B_ * L_, D_, D_);
            ln_kernel<<<B_ * L_, 128>>>(out, (const float*)pX, ga, ba, out, 0);
        }
    }
}

// round 3
// speedup vs baseline: 1.4214x; 1.4214x over previous
#include <cuda_runtime.h>
#include <cuda_bf16.h>
#include <math.h>

#define B_   4
#define L_   2048
#define D_   512
#define S_   256
#define NL_  6
#define H_   8
#define DH_  64
#define WIN_ 256

// ---------------- scratch (device globals; no allocation) ----------------
__device__ float g_X[B_*L_*D_];        // conv+silu output / proj scratch
__device__ float g_U[B_*L_*S_];        // mamba u
__device__ float g_QKV[B_*L_*3*D_];    // qkv
__device__ float g_ATT[B_*L_*D_];      // attention context
__device__ float g_HT[B_*S_];          // final ssm state
__device__ float g_STATE[B_*D_];       // per-layer state summary
__device__ float g_PART[16][B_][S_];   // ssm chunk partials

// ---------------- zero state ----------------
__global__ void zero_state_kernel() {
    int t = blockIdx.x * blockDim.x + threadIdx.x;
    if (t < B_ * D_) g_STATE[t] = 0.f;
}

// ---------------- conv (k=3, causal) + SiLU ----------------
__global__ void conv_silu_kernel(const float* __restrict__ seq,
                                 const float* __restrict__ cw) {
    int row = blockIdx.x;            // b*L + l
    int l = row & (L_ - 1);
    int t = threadIdx.x;             // 128 threads, float4 each
    float4 z = make_float4(0.f, 0.f, 0.f, 0.f);
    float4 a0 = (l >= 2) ? ((const float4*)(seq + (size_t)(row - 2) * D_))[t] : z;
    float4 a1 = (l >= 1) ? ((const float4*)(seq + (size_t)(row - 1) * D_))[t] : z;
    float4 a2 = ((const float4*)(seq + (size_t)row * D_))[t];
    float4 w0 = ((const float4*)(cw        ))[t];
    float4 w1 = ((const float4*)(cw +   D_ ))[t];
    float4 w2 = ((const float4*)(cw + 2*D_ ))[t];
    float4 x;
    x.x = w0.x*a0.x + w1.x*a1.x + w2.x*a2.x;
    x.y = w0.y*a0.y + w1.y*a1.y + w2.y*a2.y;
    x.z = w0.z*a0.z + w1.z*a1.z + w2.z*a2.z;
    x.w = w0.w*a0.w + w1.w*a1.w + w2.w*a2.w;
    x.x = x.x / (1.f + __expf(-x.x));
    x.y = x.y / (1.f + __expf(-x.y));
    x.z = x.z / (1.f + __expf(-x.z));
    x.w = x.w / (1.f + __expf(-x.w));
    ((float4*)(g_X + (size_t)row * D_))[t] = x;
}

// ---------------- bf16x3 tensor-core GEMM ----------------
// C[M,N] = A[M,K] * B (+bias), fp32 in/out, bf16 hi/lo split internally.
// TB=0: B is [K,N] row-major.  TB=1: B is [N,K] row-major.
__device__ __forceinline__ void cvt2(float x, __nv_bfloat16& h, __nv_bfloat16& l) {
    h = __float2bfloat16(x);
    l = __float2bfloat16(x - __bfloat162float(h));
}

__device__ __forceinline__ void ldsm4(unsigned& r0, unsigned& r1, unsigned& r2, unsigned& r3, unsigned addr) {
    asm volatile("ldmatrix.sync.aligned.m8n8.x4.shared.b16 {%0,%1,%2,%3},[%4];"
                 : "=r"(r0), "=r"(r1), "=r"(r2), "=r"(r3) : "r"(addr));
}
__device__ __forceinline__ void ldsm4t(unsigned& r0, unsigned& r1, unsigned& r2, unsigned& r3, unsigned addr) {
    asm volatile("ldmatrix.sync.aligned.m8n8.x4.trans.shared.b16 {%0,%1,%2,%3},[%4];"
                 : "=r"(r0), "=r"(r1), "=r"(r2), "=r"(r3) : "r"(addr));
}
__device__ __forceinline__ void mma16816(float* c, const unsigned* a, const unsigned* b) {
    asm volatile("mma.sync.aligned.m16n8k16.row.col.f32.bf16.bf16.f32 "
                 "{%0,%1,%2,%3},{%4,%5,%6,%7},{%8,%9},{%0,%1,%2,%3};"
                 : "+f"(c[0]), "+f"(c[1]), "+f"(c[2]), "+f"(c[3])
                 : "r"(a[0]), "r"(a[1]), "r"(a[2]), "r"(a[3]), "r"(b[0]), "r"(b[1]));
}

template <int TB>
__global__ void __launch_bounds__(256) mma_gemm(const float* __restrict__ A,
                                                const float* __restrict__ Bm,
                                                const float* __restrict__ bias,
                                                float* __restrict__ C,
                                                int M, int N, int K) {
    __shared__ __nv_bfloat16 Ah[128][40], Al[128][40];
    constexpr int BROWS = TB ? 64 : 32;
    constexpr int BSTR  = TB ? 40 : 72;
    __shared__ __nv_bfloat16 Bh[BROWS][BSTR], Bl[BROWS][BSTR];

    int bm = blockIdx.y * 128, bn = blockIdx.x * 64;
    int tid = threadIdx.x;
    int lane = tid & 31, wid = tid >> 5;
    int wm = (wid & 3) * 32;   // 4 warps over M
    int wn = (wid >> 2) * 32;  // 2 warps over N

    float acc[2][4][4];
#pragma unroll
    for (int i = 0; i < 2; i++)
#pragma unroll
        for (int j = 0; j < 4; j++)
#pragma unroll
            for (int k = 0; k < 4; k++) acc[i][j][k] = 0.f;

    unsigned sAh = (unsigned)__cvta_generic_to_shared(&Ah[0][0]);
    unsigned sAl = (unsigned)__cvta_generic_to_shared(&Al[0][0]);
    unsigned sBh = (unsigned)__cvta_generic_to_shared(&Bh[0][0]);
    unsigned sBl = (unsigned)__cvta_generic_to_shared(&Bl[0][0]);

    for (int k0 = 0; k0 < K; k0 += 32) {
        __syncthreads();
        // A tile 128x32
#pragma unroll
        for (int j = 0; j < 4; j++) {
            int idx = tid + 256 * j;
            int r = idx >> 3, c4 = (idx & 7) * 4;
            float4 v = *(const float4*)(A + (size_t)(bm + r) * K + k0 + c4);
            __nv_bfloat16 h0, l0, h1, l1, h2, l2, h3, l3;
            cvt2(v.x, h0, l0); cvt2(v.y, h1, l1); cvt2(v.z, h2, l2); cvt2(v.w, h3, l3);
            __nv_bfloat162 p;
            p.x = h0; p.y = h1; *(__nv_bfloat162*)&Ah[r][c4] = p;
            p.x = h2; p.y = h3; *(__nv_bfloat162*)&Ah[r][c4 + 2] = p;
            p.x = l0; p.y = l1; *(__nv_bfloat162*)&Al[r][c4] = p;
            p.x = l2; p.y = l3; *(__nv_bfloat162*)&Al[r][c4 + 2] = p;
        }
        // B tile
        if (TB == 1) {
#pragma unroll
            for (int j = 0; j < 2; j++) {
                int idx = tid + 256 * j;
                int r = idx >> 3, c4 = (idx & 7) * 4;
                float4 v = *(const float4*)(Bm + (size_t)(bn + r) * K + k0 + c4);
                __nv_bfloat16 h0, l0, h1, l1, h2, l2, h3, l3;
                cvt2(v.x, h0, l0); cvt2(v.y, h1, l1); cvt2(v.z, h2, l2); cvt2(v.w, h3, l3);
                __nv_bfloat162 p;
                p.x = h0; p.y = h1; *(__nv_bfloat162*)&Bh[r][c4] = p;
                p.x = h2; p.y = h3; *(__nv_bfloat162*)&Bh[r][c4 + 2] = p;
                p.x = l0; p.y = l1; *(__nv_bfloat162*)&Bl[r][c4] = p;
                p.x = l2; p.y = l3; *(__nv_bfloat162*)&Bl[r][c4 + 2] = p;
            }
        } else {
#pragma unroll
            for (int j = 0; j < 2; j++) {
                int idx = tid + 256 * j;
                int r = idx >> 4, c4 = (idx & 15) * 4;
                float4 v = *(const float4*)(Bm + (size_t)(k0 + r) * N + bn + c4);
                __nv_bfloat16 h0, l0, h1, l1, h2, l2, h3, l3;
                cvt2(v.x, h0, l0); cvt2(v.y, h1, l1); cvt2(v.z, h2, l2); cvt2(v.w, h3, l3);
                __nv_bfloat162 p;
                p.x = h0; p.y = h1; *(__nv_bfloat162*)&Bh[r][c4] = p;
                p.x = h2; p.y = h3; *(__nv_bfloat162*)&Bh[r][c4 + 2] = p;
                p.x = l0; p.y = l1; *(__nv_bfloat162*)&Bl[r][c4] = p;
                p.x = l2; p.y = l3; *(__nv_bfloat162*)&Bl[r][c4 + 2] = p;
            }
        }
        __syncthreads();

#pragma unroll
        for (int ks = 0; ks < 2; ks++) {
            unsigned afh[2][4], afl[2][4], bfh[4][2], bfl[4][2];
#pragma unroll
            for (int mi = 0; mi < 2; mi++) {
                int row = wm + mi * 16 + (lane & 15);
                unsigned off = (unsigned)(row * 40 + ks * 16 + (lane >> 4) * 8) * 2u;
                ldsm4(afh[mi][0], afh[mi][1], afh[mi][2], afh[mi][3], sAh + off);
                ldsm4(afl[mi][0], afl[mi][1], afl[mi][2], afl[mi][3], sAl + off);
            }
            if (TB == 1) {
#pragma unroll
                for (int nh = 0; nh < 2; nh++) {
                    int row = wn + nh * 16 + (lane & 15);
                    unsigned off = (unsigned)(row * BSTR + ks * 16 + (lane >> 4) * 8) * 2u;
                    unsigned r0, r1, r2, r3;
                    ldsm4(r0, r1, r2, r3, sBh + off);
                    bfh[nh*2+0][0] = r0; bfh[nh*2+0][1] = r2;
                    bfh[nh*2+1][0] = r1; bfh[nh*2+1][1] = r3;
                    ldsm4(r0, r1, r2, r3, sBl + off);
                    bfl[nh*2+0][0] = r0; bfl[nh*2+0][1] = r2;
                    bfl[nh*2+1][0] = r1; bfl[nh*2+1][1] = r3;
                }
            } else {
#pragma unroll
                for (int nh = 0; nh < 2; nh++) {
                    int row = ks * 16 + (lane & 15);
                    unsigned off = (unsigned)(row * BSTR + wn + nh * 16 + (lane >> 4) * 8) * 2u;
                    unsigned r0, r1, r2, r3;
                    ldsm4t(r0, r1, r2, r3, sBh + off);
                    bfh[nh*2+0][0] = r0; bfh[nh*2+0][1] = r1;
                    bfh[nh*2+1][0] = r2; bfh[nh*2+1][1] = r3;
                    ldsm4t(r0, r1, r2, r3, sBl + off);
                    bfl[nh*2+0][0] = r0; bfl[nh*2+0][1] = r1;
                    bfl[nh*2+1][0] = r2; bfl[nh*2+1][1] = r3;
                }
            }
#pragma unroll
            for (int mi = 0; mi < 2; mi++)
#pragma unroll
                for (int ni = 0; ni < 4; ni++) {
                    mma16816(acc[mi][ni], afh[mi], bfh[ni]);
                    mma16816(acc[mi][ni], afh[mi], bfl[ni]);
                    mma16816(acc[mi][ni], afl[mi], bfh[ni]);
                }
        }
    }

#pragma unroll
    for (int mi = 0; mi < 2; mi++)
#pragma unroll
        for (int ni = 0; ni < 4; ni++) {
            int r = bm + wm + mi * 16 + (lane >> 2);
            int c = bn + wn + ni * 8 + (lane & 3) * 2;
            float b0 = bias ? bias[c] : 0.f;
            float b1 = bias ? bias[c + 1] : 0.f;
            C[(size_t)r * N + c]           = acc[mi][ni][0] + b0;
            C[(size_t)r * N + c + 1]       = acc[mi][ni][1] + b1;
            C[(size_t)(r + 8) * N + c]     = acc[mi][ni][2] + b0;
            C[(size_t)(r + 8) * N + c + 1] = acc[mi][ni][3] + b1;
        }
}

// ---------------- ssm chunked Horner: coalesced over s ----------------
__global__ void ht_part_kernel(const float* __restrict__ Aparam) {
    int b = blockIdx.x, c = blockIdx.y;
    int s = threadIdx.x;   // 256
    float a = 1.f / (1.f + expf(-Aparam[s]));
    const float* base = g_U + ((size_t)(b * L_) + c * 128) * S_ + s;
    float p = 0.f;
#pragma unroll 8
    for (int j = 0; j < 128; j++) p = p * a + base[(size_t)j * S_];
    g_PART[c][b][s] = p * powf(a, (float)(128 * (15 - c)));
}

__global__ void ht_combine_kernel(const float* __restrict__ Aparam,
                                  const float* __restrict__ Wh) {
    int b = blockIdx.x;
    int s = threadIdx.x;   // 256
    float a = 1.f / (1.f + expf(-Aparam[s]));
    float h0 = 0.f;
#pragma unroll 8
    for (int d = 0; d < D_; d++) h0 += g_STATE[b * D_ + d] * Wh[(size_t)d * S_ + s];
    float sum = 0.f;
#pragma unroll
    for (int c = 0; c < 16; c++) sum += g_PART[c][b][s];
    g_HT[b * S_ + s] = powf(a, (float)L_) * h0 + sum;
}

// ---------------- state[b,d] = hT[b,:] @ Wout[:,d] ----------------
__global__ void stateout_kernel(const float* __restrict__ Wout) {
    __shared__ float ht[S_];
    int b = blockIdx.x;
    int d = threadIdx.x;   // 512
    if (d < S_) ht[d] = g_HT[b * S_ + d];
    __syncthreads();
    float acc = 0.f;
#pragma unroll 8
    for (int s = 0; s < S_; s++) acc += ht[s] * Wout[(size_t)s * D_ + d];
    g_STATE[b * D_ + d] = acc;
}

// ---------------- residual + LayerNorm ----------------
__global__ void ln_kernel(const float* __restrict__ seq, const float* __restrict__ add,
                          const float* __restrict__ gamma, const float* __restrict__ beta,
                          float* __restrict__ out, int bcast) {
    __shared__ float red[4];
    __shared__ float stat;
    int row = blockIdx.x;
    int b = row >> 11;
    int t = threadIdx.x;   // 128
    float4 x = ((const float4*)(seq + (size_t)row * D_))[t];
    const float* ap = bcast ? (g_STATE + (size_t)b * D_) : (add + (size_t)row * D_);
    float4 a4 = ((const float4*)ap)[t];
    x.x += a4.x; x.y += a4.y; x.z += a4.z; x.w += a4.w;

    float sum = x.x + x.y + x.z + x.w;
    for (int off = 16; off; off >>= 1) sum += __shfl_xor_sync(0xffffffffu, sum, off);
    if ((t & 31) == 0) red[t >> 5] = sum;
    __syncthreads();
    if (t == 0) stat = (red[0] + red[1] + red[2] + red[3]) * (1.f / D_);
    __syncthreads();
    float mu = stat;
    float d0 = x.x - mu, d1 = x.y - mu, d2 = x.z - mu, d3 = x.w - mu;
    float sq = d0*d0 + d1*d1 + d2*d2 + d3*d3;
    for (int off = 16; off; off >>= 1) sq += __shfl_xor_sync(0xffffffffu, sq, off);
    if ((t & 31) == 0) red[t >> 5] = sq;
    __syncthreads();
    if (t == 0) stat = rsqrtf((red[0] + red[1] + red[2] + red[3]) * (1.f / D_) + 1e-5f);
    __syncthreads();
    float rs = stat;
    float4 g = ((const float4*)gamma)[t], be = ((const float4*)beta)[t];
    float4 y;
    y.x = d0 * rs * g.x + be.x;
    y.y = d1 * rs * g.y + be.y;
    y.z = d2 * rs * g.z + be.z;
    y.w = d3 * rs * g.w + be.w;
    ((float4*)(out + (size_t)row * D_))[t] = y;
}

// ---------------- banded flash attention (fp32 SIMT) ----------------
__global__ void attn_kernel() {
    __shared__ float Qt[64][65];
    __shared__ float Kt[64][33];
    __shared__ float Vs[32][65];
    __shared__ float Ps[64][33];
    int b = blockIdx.z, h = blockIdx.y, qt = blockIdx.x;
    int q0 = qt * 64;
    int tid = threadIdx.x;
    int ty = tid >> 4, tx = tid & 15;

#pragma unroll
    for (int j = 0; j < 16; j++) {
        int idx = tid + 256 * j;
        int q = idx >> 6, dm = idx & 63;
        Qt[dm][q] = g_QKV[(size_t)(b * L_ + q0 + q) * (3 * D_) + h * DH_ + dm];
    }

    float m[4], lsum[4], o[4][4];
#pragma unroll
    for (int i = 0; i < 4; i++) {
        m[i] = -1e30f; lsum[i] = 0.f;
#pragma unroll
        for (int j = 0; j < 4; j++) o[i][j] = 0.f;
    }

    int kstart = q0 - WIN_; if (kstart < 0) kstart = 0;
    int kend = q0 + 64 + WIN_; if (kend > L_) kend = L_;

    for (int k0 = kstart; k0 < kend; k0 += 32) {
        __syncthreads();
#pragma unroll
        for (int j = 0; j < 8; j++) {
            int idx = tid + 256 * j;
            int kk = idx >> 6, dm = idx & 63;
            size_t base = (size_t)(b * L_ + k0 + kk) * (3 * D_) + h * DH_ + dm;
            Kt[dm][kk] = g_QKV[base + D_];
            Vs[kk][dm] = g_QKV[base + 2 * D_];
        }
        __syncthreads();

        float sc[4][2];
#pragma unroll
        for (int i = 0; i < 4; i++)
#pragma unroll
            for (int j = 0; j < 2; j++) sc[i][j] = 0.f;
#pragma unroll
        for (int kk = 0; kk < 64; kk++) {
            float av[4], bv[2];
#pragma unroll
            for (int i = 0; i < 4; i++) av[i] = Qt[kk][ty + 16 * i];
#pragma unroll
            for (int j = 0; j < 2; j++) bv[j] = Kt[kk][tx + 16 * j];
#pragma unroll
            for (int i = 0; i < 4; i++)
#pragma unroll
                for (int j = 0; j < 2; j++) sc[i][j] += av[i] * bv[j];
        }

#pragma unroll
        for (int i = 0; i < 4; i++) {
            int q = q0 + ty + 16 * i;
            float mx = -1e30f;
#pragma unroll
            for (int j = 0; j < 2; j++) {
                int k = k0 + tx + 16 * j;
                int dlt = q - k; if (dlt < 0) dlt = -dlt;
                sc[i][j] = (dlt <= WIN_) ? sc[i][j] * 0.125f : -1e30f;
                mx = fmaxf(mx, sc[i][j]);
            }
            for (int off = 8; off; off >>= 1)
                mx = fmaxf(mx, __shfl_xor_sync(0xffffffffu, mx, off));
            float mn = fmaxf(m[i], mx);
            float corr = __expf(m[i] - mn);
            float rs = 0.f;
#pragma unroll
            for (int j = 0; j < 2; j++) {
                float p = (sc[i][j] > -1e29f) ? __expf(sc[i][j] - mn) : 0.f;
                Ps[ty + 16 * i][tx + 16 * j] = p;
                rs += p;
            }
            for (int off = 8; off; off >>= 1)
                rs += __shfl_xor_sync(0xffffffffu, rs, off);
            lsum[i] = lsum[i] * corr + rs;
            m[i] = mn;
#pragma unroll
            for (int j = 0; j < 4; j++) o[i][j] *= corr;
        }
        __syncthreads();

#pragma unroll
        for (int kk = 0; kk < 32; kk++) {
            float pv[4], vv[4];
#pragma unroll
            for (int i = 0; i < 4; i++) pv[i] = Ps[ty + 16 * i][kk];
#pragma unroll
            for (int j = 0; j < 4; j++) vv[j] = Vs[kk][tx + 16 * j];
#pragma unroll
            for (int i = 0; i < 4; i++)
#pragma unroll
                for (int j = 0; j < 4; j++) o[i][j] += pv[i] * vv[j];
        }
    }

#pragma unroll
    for (int i = 0; i < 4; i++) {
        float inv = 1.f / lsum[i];
        int q = q0 + ty + 16 * i;
#pragma unroll
        for (int j = 0; j < 4; j++)
            g_ATT[(size_t)(b * L_ + q) * D_ + h * DH_ + tx + 16 * j] = o[i][j] * inv;
    }
}

// ---------------- launcher ----------------
extern "C" void kernel_launch(void* const* d_in, const int* in_sizes, int n_in,
                              void* d_out, int out_size) {
    const float* context = (const float*)d_in[0];
    const float* conv_w  = (const float*)d_in[1];
    const float* Wx      = (const float*)d_in[2];
    const float* Wh      = (const float*)d_in[3];
    const float* Wout    = (const float*)d_in[4];
    const float* Aparam  = (const float*)d_in[5];
    const float* gm      = (const float*)d_in[6];
    const float* bm      = (const float*)d_in[7];
    const float* ga      = (const float*)d_in[8];
    const float* ba      = (const float*)d_in[9];
    const float* Wqkv    = (const float*)d_in[10];
    const float* bqkv    = (const float*)d_in[11];
    const float* Wo      = (const float*)d_in[12];
    const float* bo      = (const float*)d_in[13];
    float* out = (float*)d_out;

    static void *pX = nullptr, *pU = nullptr, *pQKV = nullptr, *pATT = nullptr;
    if (!pX) {
        cudaGetSymbolAddress(&pX, g_X);
        cudaGetSymbolAddress(&pU, g_U);
        cudaGetSymbolAddress(&pQKV, g_QKV);
        cudaGetSymbolAddress(&pATT, g_ATT);
    }

    zero_state_kernel<<<(B_ * D_ + 255) / 256, 256>>>();

    for (int i = 0; i < NL_; i++) {
        const float* seqin = (i == 0) ? context : out;
        conv_silu_kernel<<<B_ * L_, 128>>>(seqin, conv_w + (size_t)i * 3 * D_);
        mma_gemm<0><<<dim3(S_ / 64, B_ * L_ / 128), 256>>>(
            (const float*)pX, Wx + (size_t)i * D_ * S_, nullptr, (float*)pU,
            B_ * L_, S_, D_);
        ht_part_kernel<<<dim3(B_, 16), 256>>>(Aparam + (size_t)i * S_);
        ht_combine_kernel<<<B_, 256>>>(Aparam + (size_t)i * S_, Wh + (size_t)i * D_ * S_);
        stateout_kernel<<<B_, D_>>>(Wout + (size_t)i * S_ * D_);
        ln_kernel<<<B_ * L_, 128>>>(seqin, nullptr, gm, bm, out, 1);

        if (((i + 1) % 4) == 0) {
            mma_gemm<1><<<dim3(3 * D_ / 64, B_ * L_ / 128), 256>>>(
                out, Wqkv, bqkv, (float*)pQKV, B_ * L_, 3 * D_, D_);
            attn_kernel<<<dim3(L_ / 64, H_, B_), 256>>>();
            mma_gemm<1><<<dim3(D_ / 64, B_ * L_ / 128), 256>>>(
                (const float*)pATT, Wo, bo, (float*)pX, B_ * L_, D_, D_);
            ln_kernel<<<B_ * L_, 128>>>(out, (const float*)pX, ga, ba, out, 0);
        }
    }
}

// round 4
// speedup vs baseline: 1.9726x; 1.3878x over previous
#include <cuda_runtime.h>
#include <cuda_bf16.h>
#include <math.h>

#define B_   4
#define L_   2048
#define D_   512
#define S_   256
#define NL_  6
#define H_   8
#define DH_  64
#define WIN_ 256

// ---------------- scratch (device globals; no allocation) ----------------
__device__ float g_X[B_*L_*D_];        // conv+silu output / proj scratch
__device__ float g_U[B_*L_*S_];        // mamba u
__device__ float g_QKV[B_*L_*3*D_];    // qkv
__device__ float g_ATT[B_*L_*D_];      // attention context
__device__ float g_HT[B_*S_];          // final ssm state
__device__ float g_STATE[B_*D_];       // per-layer state summary
__device__ float g_PART[64][B_][S_];   // ssm chunk partials

// ---------------- zero state ----------------
__global__ void zero_state_kernel() {
    int t = blockIdx.x * blockDim.x + threadIdx.x;
    if (t < B_ * D_) g_STATE[t] = 0.f;
}

// ---------------- conv (k=3, causal) + SiLU ----------------
__global__ void conv_silu_kernel(const float* __restrict__ seq,
                                 const float* __restrict__ cw) {
    int row = blockIdx.x;            // b*L + l
    int l = row & (L_ - 1);
    int t = threadIdx.x;             // 128 threads, float4 each
    float4 z = make_float4(0.f, 0.f, 0.f, 0.f);
    float4 a0 = (l >= 2) ? ((const float4*)(seq + (size_t)(row - 2) * D_))[t] : z;
    float4 a1 = (l >= 1) ? ((const float4*)(seq + (size_t)(row - 1) * D_))[t] : z;
    float4 a2 = ((const float4*)(seq + (size_t)row * D_))[t];
    float4 w0 = ((const float4*)(cw        ))[t];
    float4 w1 = ((const float4*)(cw +   D_ ))[t];
    float4 w2 = ((const float4*)(cw + 2*D_ ))[t];
    float4 x;
    x.x = w0.x*a0.x + w1.x*a1.x + w2.x*a2.x;
    x.y = w0.y*a0.y + w1.y*a1.y + w2.y*a2.y;
    x.z = w0.z*a0.z + w1.z*a1.z + w2.z*a2.z;
    x.w = w0.w*a0.w + w1.w*a1.w + w2.w*a2.w;
    x.x = x.x / (1.f + __expf(-x.x));
    x.y = x.y / (1.f + __expf(-x.y));
    x.z = x.z / (1.f + __expf(-x.z));
    x.w = x.w / (1.f + __expf(-x.w));
    ((float4*)(g_X + (size_t)row * D_))[t] = x;
}

// ---------------- bf16x3 helpers ----------------
__device__ __forceinline__ void cvt2(float x, __nv_bfloat16& h, __nv_bfloat16& l) {
    h = __float2bfloat16(x);
    l = __float2bfloat16(x - __bfloat162float(h));
}
__device__ __forceinline__ void ldsm4(unsigned& r0, unsigned& r1, unsigned& r2, unsigned& r3, unsigned addr) {
    asm volatile("ldmatrix.sync.aligned.m8n8.x4.shared.b16 {%0,%1,%2,%3},[%4];"
                 : "=r"(r0), "=r"(r1), "=r"(r2), "=r"(r3) : "r"(addr));
}
__device__ __forceinline__ void ldsm4t(unsigned& r0, unsigned& r1, unsigned& r2, unsigned& r3, unsigned addr) {
    asm volatile("ldmatrix.sync.aligned.m8n8.x4.trans.shared.b16 {%0,%1,%2,%3},[%4];"
                 : "=r"(r0), "=r"(r1), "=r"(r2), "=r"(r3) : "r"(addr));
}
__device__ __forceinline__ void mma16816(float* c, const unsigned* a, const unsigned* b) {
    asm volatile("mma.sync.aligned.m16n8k16.row.col.f32.bf16.bf16.f32 "
                 "{%0,%1,%2,%3},{%4,%5,%6,%7},{%8,%9},{%0,%1,%2,%3};"
                 : "+f"(c[0]), "+f"(c[1]), "+f"(c[2]), "+f"(c[3])
                 : "r"(a[0]), "r"(a[1]), "r"(a[2]), "r"(a[3]), "r"(b[0]), "r"(b[1]));
}
__device__ __forceinline__ unsigned pack_bf16x2(float x, float y) {
    __nv_bfloat162 p;
    p.x = __float2bfloat16(x);
    p.y = __float2bfloat16(y);
    return *(unsigned*)&p;
}

// ---------------- bf16x3 tensor-core GEMM with register prefetch ----------
// C[M,N] = A[M,K] * B (+bias). TB=0: B[K,N].  TB=1: B[N,K].
template <int TB>
__global__ void __launch_bounds__(256) mma_gemm(const float* __restrict__ A,
                                                const float* __restrict__ Bm,
                                                const float* __restrict__ bias,
                                                float* __restrict__ C,
                                                int M, int N, int K) {
    __shared__ __nv_bfloat16 Ah[128][40], Al[128][40];
    constexpr int BROWS = TB ? 64 : 32;
    constexpr int BSTR  = TB ? 40 : 72;
    __shared__ __nv_bfloat16 Bh[BROWS][BSTR], Bl[BROWS][BSTR];

    int bm = blockIdx.y * 128, bn = blockIdx.x * 64;
    int tid = threadIdx.x;
    int lane = tid & 31, wid = tid >> 5;
    int wm = (wid & 3) * 32;
    int wn = (wid >> 2) * 32;

    float acc[2][4][4];
#pragma unroll
    for (int i = 0; i < 2; i++)
#pragma unroll
        for (int j = 0; j < 4; j++)
#pragma unroll
            for (int k = 0; k < 4; k++) acc[i][j][k] = 0.f;

    unsigned sAh = (unsigned)__cvta_generic_to_shared(&Ah[0][0]);
    unsigned sAl = (unsigned)__cvta_generic_to_shared(&Al[0][0]);
    unsigned sBh = (unsigned)__cvta_generic_to_shared(&Bh[0][0]);
    unsigned sBl = (unsigned)__cvta_generic_to_shared(&Bl[0][0]);

    float4 ra[4], rb[2];
    // prologue load k0 = 0
#pragma unroll
    for (int j = 0; j < 4; j++) {
        int idx = tid + 256 * j;
        int r = idx >> 3, c4 = (idx & 7) * 4;
        ra[j] = *(const float4*)(A + (size_t)(bm + r) * K + c4);
    }
    if (TB == 1) {
#pragma unroll
        for (int j = 0; j < 2; j++) {
            int idx = tid + 256 * j;
            int r = idx >> 3, c4 = (idx & 7) * 4;
            rb[j] = *(const float4*)(Bm + (size_t)(bn + r) * K + c4);
        }
    } else {
#pragma unroll
        for (int j = 0; j < 2; j++) {
            int idx = tid + 256 * j;
            int r = idx >> 4, c4 = (idx & 15) * 4;
            rb[j] = *(const float4*)(Bm + (size_t)r * N + bn + c4);
        }
    }

    for (int k0 = 0; k0 < K; k0 += 32) {
        // store staged regs to smem
#pragma unroll
        for (int j = 0; j < 4; j++) {
            int idx = tid + 256 * j;
            int r = idx >> 3, c4 = (idx & 7) * 4;
            __nv_bfloat16 h0, l0, h1, l1, h2, l2, h3, l3;
            cvt2(ra[j].x, h0, l0); cvt2(ra[j].y, h1, l1); cvt2(ra[j].z, h2, l2); cvt2(ra[j].w, h3, l3);
            __nv_bfloat162 p;
            p.x = h0; p.y = h1; *(__nv_bfloat162*)&Ah[r][c4] = p;
            p.x = h2; p.y = h3; *(__nv_bfloat162*)&Ah[r][c4 + 2] = p;
            p.x = l0; p.y = l1; *(__nv_bfloat162*)&Al[r][c4] = p;
            p.x = l2; p.y = l3; *(__nv_bfloat162*)&Al[r][c4 + 2] = p;
        }
#pragma unroll
        for (int j = 0; j < 2; j++) {
            int idx = tid + 256 * j;
            int r = TB ? (idx >> 3) : (idx >> 4);
            int c4 = TB ? (idx & 7) * 4 : (idx & 15) * 4;
            __nv_bfloat16 h0, l0, h1, l1, h2, l2, h3, l3;
            cvt2(rb[j].x, h0, l0); cvt2(rb[j].y, h1, l1); cvt2(rb[j].z, h2, l2); cvt2(rb[j].w, h3, l3);
            __nv_bfloat162 p;
            p.x = h0; p.y = h1; *(__nv_bfloat162*)&Bh[r][c4] = p;
            p.x = h2; p.y = h3; *(__nv_bfloat162*)&Bh[r][c4 + 2] = p;
            p.x = l0; p.y = l1; *(__nv_bfloat162*)&Bl[r][c4] = p;
            p.x = l2; p.y = l3; *(__nv_bfloat162*)&Bl[r][c4 + 2] = p;
        }
        __syncthreads();

        // prefetch next tile while MMAs run
        int kn = k0 + 32;
        if (kn < K) {
#pragma unroll
            for (int j = 0; j < 4; j++) {
                int idx = tid + 256 * j;
                int r = idx >> 3, c4 = (idx & 7) * 4;
                ra[j] = *(const float4*)(A + (size_t)(bm + r) * K + kn + c4);
            }
            if (TB == 1) {
#pragma unroll
                for (int j = 0; j < 2; j++) {
                    int idx = tid + 256 * j;
                    int r = idx >> 3, c4 = (idx & 7) * 4;
                    rb[j] = *(const float4*)(Bm + (size_t)(bn + r) * K + kn + c4);
                }
            } else {
#pragma unroll
                for (int j = 0; j < 2; j++) {
                    int idx = tid + 256 * j;
                    int r = idx >> 4, c4 = (idx & 15) * 4;
                    rb[j] = *(const float4*)(Bm + (size_t)(kn + r) * N + bn + c4);
                }
            }
        }

#pragma unroll
        for (int ks = 0; ks < 2; ks++) {
            unsigned afh[2][4], afl[2][4], bfh[4][2], bfl[4][2];
#pragma unroll
            for (int mi = 0; mi < 2; mi++) {
                int row = wm + mi * 16 + (lane & 15);
                unsigned off = (unsigned)(row * 40 + ks * 16 + (lane >> 4) * 8) * 2u;
                ldsm4(afh[mi][0], afh[mi][1], afh[mi][2], afh[mi][3], sAh + off);
                ldsm4(afl[mi][0], afl[mi][1], afl[mi][2], afl[mi][3], sAl + off);
            }
            if (TB == 1) {
#pragma unroll
                for (int nh = 0; nh < 2; nh++) {
                    int row = wn + nh * 16 + (lane & 15);
                    unsigned off = (unsigned)(row * BSTR + ks * 16 + (lane >> 4) * 8) * 2u;
                    unsigned r0, r1, r2, r3;
                    ldsm4(r0, r1, r2, r3, sBh + off);
                    bfh[nh*2+0][0] = r0; bfh[nh*2+0][1] = r2;
                    bfh[nh*2+1][0] = r1; bfh[nh*2+1][1] = r3;
                    ldsm4(r0, r1, r2, r3, sBl + off);
                    bfl[nh*2+0][0] = r0; bfl[nh*2+0][1] = r2;
                    bfl[nh*2+1][0] = r1; bfl[nh*2+1][1] = r3;
                }
            } else {
#pragma unroll
                for (int nh = 0; nh < 2; nh++) {
                    int row = ks * 16 + (lane & 15);
                    unsigned off = (unsigned)(row * BSTR + wn + nh * 16 + (lane >> 4) * 8) * 2u;
                    unsigned r0, r1, r2, r3;
                    ldsm4t(r0, r1, r2, r3, sBh + off);
                    bfh[nh*2+0][0] = r0; bfh[nh*2+0][1] = r1;
                    bfh[nh*2+1][0] = r2; bfh[nh*2+1][1] = r3;
                    ldsm4t(r0, r1, r2, r3, sBl + off);
                    bfl[nh*2+0][0] = r0; bfl[nh*2+0][1] = r1;
                    bfl[nh*2+1][0] = r2; bfl[nh*2+1][1] = r3;
                }
            }
#pragma unroll
            for (int mi = 0; mi < 2; mi++)
#pragma unroll
                for (int ni = 0; ni < 4; ni++) {
                    mma16816(acc[mi][ni], afh[mi], bfh[ni]);
                    mma16816(acc[mi][ni], afh[mi], bfl[ni]);
                    mma16816(acc[mi][ni], afl[mi], bfh[ni]);
                }
        }
        __syncthreads();
    }

#pragma unroll
    for (int mi = 0; mi < 2; mi++)
#pragma unroll
        for (int ni = 0; ni < 4; ni++) {
            int r = bm + wm + mi * 16 + (lane >> 2);
            int c = bn + wn + ni * 8 + (lane & 3) * 2;
            float b0 = bias ? bias[c] : 0.f;
            float b1 = bias ? bias[c + 1] : 0.f;
            C[(size_t)r * N + c]           = acc[mi][ni][0] + b0;
            C[(size_t)r * N + c + 1]       = acc[mi][ni][1] + b1;
            C[(size_t)(r + 8) * N + c]     = acc[mi][ni][2] + b0;
            C[(size_t)(r + 8) * N + c + 1] = acc[mi][ni][3] + b1;
        }
}

// ---------------- ssm chunked Horner with decay skip ----------------
__global__ void ht_part_kernel(const float* __restrict__ Aparam) {
    int b = blockIdx.x, c = blockIdx.y;   // 64 chunks of 32
    int s = threadIdx.x;                  // 256
    float a = 1.f / (1.f + expf(-Aparam[s]));
    float wt = powf(a, (float)(32 * (63 - c)));
    float wmax = wt;
    for (int off = 16; off; off >>= 1)
        wmax = fmaxf(wmax, __shfl_xor_sync(0xffffffffu, wmax, off));
    if (wmax < 1e-28f) { g_PART[c][b][s] = 0.f; return; }
    const float* base = g_U + ((size_t)(b * L_) + c * 32) * S_ + s;
    float p = 0.f;
#pragma unroll
    for (int j = 0; j < 32; j++) p = p * a + base[(size_t)j * S_];
    g_PART[c][b][s] = p * wt;
}

__global__ void ht_combine_kernel(const float* __restrict__ Aparam,
                                  const float* __restrict__ Wh) {
    int b = blockIdx.x;
    int s = threadIdx.x;   // 256
    float a = 1.f / (1.f + expf(-Aparam[s]));
    float h0 = 0.f;
#pragma unroll 8
    for (int d = 0; d < D_; d++) h0 += g_STATE[b * D_ + d] * Wh[(size_t)d * S_ + s];
    float sum = 0.f;
#pragma unroll
    for (int c = 0; c < 64; c++) sum += g_PART[c][b][s];
    g_HT[b * S_ + s] = powf(a, (float)L_) * h0 + sum;
}

// ---------------- state[b,d] = hT[b,:] @ Wout[:,d] ----------------
__global__ void stateout_kernel(const float* __restrict__ Wout) {
    __shared__ float ht[S_];
    int b = blockIdx.x;
    int d = threadIdx.x;   // 512
    if (d < S_) ht[d] = g_HT[b * S_ + d];
    __syncthreads();
    float acc = 0.f;
#pragma unroll 8
    for (int s = 0; s < S_; s++) acc += ht[s] * Wout[(size_t)s * D_ + d];
    g_STATE[b * D_ + d] = acc;
}

// ---------------- residual + LayerNorm ----------------
__global__ void ln_kernel(const float* __restrict__ seq, const float* __restrict__ add,
                          const float* __restrict__ gamma, const float* __restrict__ beta,
                          float* __restrict__ out, int bcast) {
    __shared__ float red[4];
    __shared__ float stat;
    int row = blockIdx.x;
    int b = row >> 11;
    int t = threadIdx.x;   // 128
    float4 x = ((const float4*)(seq + (size_t)row * D_))[t];
    const float* ap = bcast ? (g_STATE + (size_t)b * D_) : (add + (size_t)row * D_);
    float4 a4 = ((const float4*)ap)[t];
    x.x += a4.x; x.y += a4.y; x.z += a4.z; x.w += a4.w;

    float sum = x.x + x.y + x.z + x.w;
    for (int off = 16; off; off >>= 1) sum += __shfl_xor_sync(0xffffffffu, sum, off);
    if ((t & 31) == 0) red[t >> 5] = sum;
    __syncthreads();
    if (t == 0) stat = (red[0] + red[1] + red[2] + red[3]) * (1.f / D_);
    __syncthreads();
    float mu = stat;
    float d0 = x.x - mu, d1 = x.y - mu, d2 = x.z - mu, d3 = x.w - mu;
    float sq = d0*d0 + d1*d1 + d2*d2 + d3*d3;
    for (int off = 16; off; off >>= 1) sq += __shfl_xor_sync(0xffffffffu, sq, off);
    if ((t & 31) == 0) red[t >> 5] = sq;
    __syncthreads();
    if (t == 0) stat = rsqrtf((red[0] + red[1] + red[2] + red[3]) * (1.f / D_) + 1e-5f);
    __syncthreads();
    float rs = stat;
    float4 g = ((const float4*)gamma)[t], be = ((const float4*)beta)[t];
    float4 y;
    y.x = d0 * rs * g.x + be.x;
    y.y = d1 * rs * g.y + be.y;
    y.z = d2 * rs * g.z + be.z;
    y.w = d3 * rs * g.w + be.w;
    ((float4*)(out + (size_t)row * D_))[t] = y;
}

// ---------------- banded flash attention with tensor cores ----------------
// block = (qt, h, b), 128 threads (4 warps), 64 queries, k-tiles of 64.
// bf16 3-term hi/lo split on both QK^T and P*V.
#define ATT_STR 72
extern __shared__ __nv_bfloat16 s_att[];

__global__ void __launch_bounds__(128) attn_mma_kernel() {
    __nv_bfloat16* Qh = s_att;
    __nv_bfloat16* Ql = Qh + 64 * ATT_STR;
    __nv_bfloat16* Kh = Ql + 64 * ATT_STR;
    __nv_bfloat16* Kl = Kh + 64 * ATT_STR;
    __nv_bfloat16* Vh = Kl + 64 * ATT_STR;
    __nv_bfloat16* Vl = Vh + 64 * ATT_STR;

    int b = blockIdx.z, h = blockIdx.y, q0 = blockIdx.x * 64;
    int tid = threadIdx.x, lane = tid & 31, w = tid >> 5;

    unsigned sQh = (unsigned)__cvta_generic_to_shared(Qh);
    unsigned sQl = (unsigned)__cvta_generic_to_shared(Ql);
    unsigned sKh = (unsigned)__cvta_generic_to_shared(Kh);
    unsigned sKl = (unsigned)__cvta_generic_to_shared(Kl);
    unsigned sVh = (unsigned)__cvta_generic_to_shared(Vh);
    unsigned sVl = (unsigned)__cvta_generic_to_shared(Vl);

    // load Q tile 64x64
#pragma unroll
    for (int j = 0; j < 8; j++) {
        int idx = tid + 128 * j;
        int r = idx >> 4, c4 = (idx & 15) * 4;
        float4 v = *(const float4*)(g_QKV + (size_t)(b * L_ + q0 + r) * (3 * D_) + h * DH_ + c4);
        __nv_bfloat16 h0, l0, h1, l1, h2, l2, h3, l3;
        cvt2(v.x, h0, l0); cvt2(v.y, h1, l1); cvt2(v.z, h2, l2); cvt2(v.w, h3, l3);
        __nv_bfloat162 p;
        p.x = h0; p.y = h1; *(__nv_bfloat162*)&Qh[r * ATT_STR + c4] = p;
        p.x = h2; p.y = h3; *(__nv_bfloat162*)&Qh[r * ATT_STR + c4 + 2] = p;
        p.x = l0; p.y = l1; *(__nv_bfloat162*)&Ql[r * ATT_STR + c4] = p;
        p.x = l2; p.y = l3; *(__nv_bfloat162*)&Ql[r * ATT_STR + c4 + 2] = p;
    }

    float m0 = -1e30f, m1 = -1e30f, l0s = 0.f, l1s = 0.f;
    float o[8][4];
#pragma unroll
    for (int j = 0; j < 8; j++)
#pragma unroll
        for (int r = 0; r < 4; r++) o[j][r] = 0.f;

    int qrow0 = 16 * w + (lane >> 2);       // local q row (first)
    int kstart = q0 - WIN_; if (kstart < 0) kstart = 0;
    int kend = q0 + 64 + WIN_; if (kend > L_) kend = L_;

    for (int k0 = kstart; k0 < kend; k0 += 64) {
        __syncthreads();
        // load K,V tiles 64x64 each
#pragma unroll
        for (int j = 0; j < 8; j++) {
            int idx = tid + 128 * j;
            int r = idx >> 4, c4 = (idx & 15) * 4;
            size_t base = (size_t)(b * L_ + k0 + r) * (3 * D_) + h * DH_ + c4;
            float4 kv = *(const float4*)(g_QKV + base + D_);
            float4 vv = *(const float4*)(g_QKV + base + 2 * D_);
            __nv_bfloat16 h0, l0, h1, l1, h2, l2, h3, l3;
            cvt2(kv.x, h0, l0); cvt2(kv.y, h1, l1); cvt2(kv.z, h2, l2); cvt2(kv.w, h3, l3);
            __nv_bfloat162 p;
            p.x = h0; p.y = h1; *(__nv_bfloat162*)&Kh[r * ATT_STR + c4] = p;
            p.x = h2; p.y = h3; *(__nv_bfloat162*)&Kh[r * ATT_STR + c4 + 2] = p;
            p.x = l0; p.y = l1; *(__nv_bfloat162*)&Kl[r * ATT_STR + c4] = p;
            p.x = l2; p.y = l3; *(__nv_bfloat162*)&Kl[r * ATT_STR + c4 + 2] = p;
            cvt2(vv.x, h0, l0); cvt2(vv.y, h1, l1); cvt2(vv.z, h2, l2); cvt2(vv.w, h3, l3);
            p.x = h0; p.y = h1; *(__nv_bfloat162*)&Vh[r * ATT_STR + c4] = p;
            p.x = h2; p.y = h3; *(__nv_bfloat162*)&Vh[r * ATT_STR + c4 + 2] = p;
            p.x = l0; p.y = l1; *(__nv_bfloat162*)&Vl[r * ATT_STR + c4] = p;
            p.x = l2; p.y = l3; *(__nv_bfloat162*)&Vl[r * ATT_STR + c4 + 2] = p;
        }
        __syncthreads();

        // S = Q K^T (3-term bf16 split), warp handles 16 q rows x 64 keys
        float sc[8][4];
#pragma unroll
        for (int j = 0; j < 8; j++)
#pragma unroll
            for (int r = 0; r < 4; r++) sc[j][r] = 0.f;

#pragma unroll
        for (int kk = 0; kk < 4; kk++) {
            unsigned aqh[4], aql[4];
            int qrow = 16 * w + (lane & 15);
            unsigned qoff = (unsigned)(qrow * ATT_STR + kk * 16 + (lane >> 4) * 8) * 2u;
            ldsm4(aqh[0], aqh[1], aqh[2], aqh[3], sQh + qoff);
            ldsm4(aql[0], aql[1], aql[2], aql[3], sQl + qoff);
#pragma unroll
            for (int nh = 0; nh < 4; nh++) {
                int krow = nh * 16 + (lane & 15);
                unsigned koff = (unsigned)(krow * ATT_STR + kk * 16 + (lane >> 4) * 8) * 2u;
                unsigned r0, r1, r2, r3;
                unsigned bh0[2], bh1[2], bl0[2], bl1[2];
                ldsm4(r0, r1, r2, r3, sKh + koff);
                bh0[0] = r0; bh0[1] = r2; bh1[0] = r1; bh1[1] = r3;
                ldsm4(r0, r1, r2, r3, sKl + koff);
                bl0[0] = r0; bl0[1] = r2; bl1[0] = r1; bl1[1] = r3;
                mma16816(sc[2*nh],   aqh, bh0);
                mma16816(sc[2*nh],   aql, bh0);
                mma16816(sc[2*nh],   aqh, bl0);
                mma16816(sc[2*nh+1], aqh, bh1);
                mma16816(sc[2*nh+1], aql, bh1);
                mma16816(sc[2*nh+1], aqh, bl1);
            }
        }

        // mask + scale
        int q_a = q0 + qrow0, q_b = q_a + 8;
#pragma unroll
        for (int j = 0; j < 8; j++) {
#pragma unroll
            for (int r = 0; r < 4; r++) {
                int k = k0 + j * 8 + (lane & 3) * 2 + (r & 1);
                int q = (r < 2) ? q_a : q_b;
                int dlt = q - k; if (dlt < 0) dlt = -dlt;
                sc[j][r] = (dlt <= WIN_) ? sc[j][r] * 0.125f : -1e30f;
            }
        }
        // row max
        float mx0 = -1e30f, mx1 = -1e30f;
#pragma unroll
        for (int j = 0; j < 8; j++) {
            mx0 = fmaxf(mx0, fmaxf(sc[j][0], sc[j][1]));
            mx1 = fmaxf(mx1, fmaxf(sc[j][2], sc[j][3]));
        }
        for (int off = 1; off < 4; off <<= 1) {
            mx0 = fmaxf(mx0, __shfl_xor_sync(0xffffffffu, mx0, off));
            mx1 = fmaxf(mx1, __shfl_xor_sync(0xffffffffu, mx1, off));
        }
        float mn0 = fmaxf(m0, mx0), mn1 = fmaxf(m1, mx1);
        float c0 = __expf(m0 - mn0), c1 = __expf(m1 - mn1);
        float rs0 = 0.f, rs1 = 0.f;
#pragma unroll
        for (int j = 0; j < 8; j++) {
            sc[j][0] = __expf(sc[j][0] - mn0);
            sc[j][1] = __expf(sc[j][1] - mn0);
            sc[j][2] = __expf(sc[j][2] - mn1);
            sc[j][3] = __expf(sc[j][3] - mn1);
            rs0 += sc[j][0] + sc[j][1];
            rs1 += sc[j][2] + sc[j][3];
        }
        for (int off = 1; off < 4; off <<= 1) {
            rs0 += __shfl_xor_sync(0xffffffffu, rs0, off);
            rs1 += __shfl_xor_sync(0xffffffffu, rs1, off);
        }
        l0s = l0s * c0 + rs0;
        l1s = l1s * c1 + rs1;
        m0 = mn0; m1 = mn1;
#pragma unroll
        for (int j = 0; j < 8; j++) {
            o[j][0] *= c0; o[j][1] *= c0;
            o[j][2] *= c1; o[j][3] *= c1;
        }

        // O += P V (3-term bf16 split)
#pragma unroll
        for (int kc = 0; kc < 4; kc++) {
            unsigned ph[4], pl[4];
            {
                float x0 = sc[2*kc][0],   x1 = sc[2*kc][1];
                float x2 = sc[2*kc][2],   x3 = sc[2*kc][3];
                float y0 = sc[2*kc+1][0], y1 = sc[2*kc+1][1];
                float y2 = sc[2*kc+1][2], y3 = sc[2*kc+1][3];
                ph[0] = pack_bf16x2(x0, x1);
                ph[1] = pack_bf16x2(x2, x3);
                ph[2] = pack_bf16x2(y0, y1);
                ph[3] = pack_bf16x2(y2, y3);
                pl[0] = pack_bf16x2(x0 - __bfloat162float(__float2bfloat16(x0)),
                                    x1 - __bfloat162float(__float2bfloat16(x1)));
                pl[1] = pack_bf16x2(x2 - __bfloat162float(__float2bfloat16(x2)),
                                    x3 - __bfloat162float(__float2bfloat16(x3)));
                pl[2] = pack_bf16x2(y0 - __bfloat162float(__float2bfloat16(y0)),
                                    y1 - __bfloat162float(__float2bfloat16(y1)));
                pl[3] = pack_bf16x2(y2 - __bfloat162float(__float2bfloat16(y2)),
                                    y3 - __bfloat162float(__float2bfloat16(y3)));
            }
#pragma unroll
            for (int nh = 0; nh < 4; nh++) {
                int vrow = kc * 16 + (lane & 15);
                unsigned voff = (unsigned)(vrow * ATT_STR + nh * 16 + (lane >> 4) * 8) * 2u;
                unsigned r0, r1, r2, r3;
                unsigned bh0[2], bh1[2], bl0[2], bl1[2];
                ldsm4t(r0, r1, r2, r3, sVh + voff);
                bh0[0] = r0; bh0[1] = r1; bh1[0] = r2; bh1[1] = r3;
                ldsm4t(r0, r1, r2, r3, sVl + voff);
                bl0[0] = r0; bl0[1] = r1; bl1[0] = r2; bl1[1] = r3;
                mma16816(o[2*nh],   ph, bh0);
                mma16816(o[2*nh],   pl, bh0);
                mma16816(o[2*nh],   ph, bl0);
                mma16816(o[2*nh+1], ph, bh1);
                mma16816(o[2*nh+1], pl, bh1);
                mma16816(o[2*nh+1], ph, bl1);
            }
        }
    }

    // epilogue
    float inv0 = 1.f / l0s, inv1 = 1.f / l1s;
    int qa = b * L_ + q0 + qrow0;
#pragma unroll
    for (int j = 0; j < 8; j++) {
        int c = h * DH_ + j * 8 + (lane & 3) * 2;
        g_ATT[(size_t)qa * D_ + c]           = o[j][0] * inv0;
        g_ATT[(size_t)qa * D_ + c + 1]       = o[j][1] * inv0;
        g_ATT[(size_t)(qa + 8) * D_ + c]     = o[j][2] * inv1;
        g_ATT[(size_t)(qa + 8) * D_ + c + 1] = o[j][3] * inv1;
    }
}

// ---------------- launcher ----------------
extern "C" void kernel_launch(void* const* d_in, const int* in_sizes, int n_in,
                              void* d_out, int out_size) {
    const float* context = (const float*)d_in[0];
    const float* conv_w  = (const float*)d_in[1];
    const float* Wx      = (const float*)d_in[2];
    const float* Wh      = (const float*)d_in[3];
    const float* Wout    = (const float*)d_in[4];
    const float* Aparam  = (const float*)d_in[5];
    const float* gm      = (const float*)d_in[6];
    const float* bm      = (const float*)d_in[7];
    const float* ga      = (const float*)d_in[8];
    const float* ba      = (const float*)d_in[9];
    const float* Wqkv    = (const float*)d_in[10];
    const float* bqkv    = (const float*)d_in[11];
    const float* Wo      = (const float*)d_in[12];
    const float* bo      = (const float*)d_in[13];
    float* out = (float*)d_out;

    static void *pX = nullptr, *pU = nullptr, *pQKV = nullptr, *pATT = nullptr;
    if (!pX) {
        cudaGetSymbolAddress(&pX, g_X);
        cudaGetSymbolAddress(&pU, g_U);
        cudaGetSymbolAddress(&pQKV, g_QKV);
        cudaGetSymbolAddress(&pATT, g_ATT);
        cudaFuncSetAttribute(attn_mma_kernel,
                             cudaFuncAttributeMaxDynamicSharedMemorySize,
                             6 * 64 * ATT_STR * (int)sizeof(__nv_bfloat16));
    }

    zero_state_kernel<<<(B_ * D_ + 255) / 256, 256>>>();

    for (int i = 0; i < NL_; i++) {
        const float* seqin = (i == 0) ? context : out;
        conv_silu_kernel<<<B_ * L_, 128>>>(seqin, conv_w + (size_t)i * 3 * D_);
        mma_gemm<0><<<dim3(S_ / 64, B_ * L_ / 128), 256>>>(
            (const float*)pX, Wx + (size_t)i * D_ * S_, nullptr, (float*)pU,
            B_ * L_, S_, D_);
        ht_part_kernel<<<dim3(B_, 64), 256>>>(Aparam + (size_t)i * S_);
        ht_combine_kernel<<<B_, 256>>>(Aparam + (size_t)i * S_, Wh + (size_t)i * D_ * S_);
        stateout_kernel<<<B_, D_>>>(Wout + (size_t)i * S_ * D_);
        ln_kernel<<<B_ * L_, 128>>>(seqin, nullptr, gm, bm, out, 1);

        if (((i + 1) % 4) == 0) {
            mma_gemm<1><<<dim3(3 * D_ / 64, B_ * L_ / 128), 256>>>(
                out, Wqkv, bqkv, (float*)pQKV, B_ * L_, 3 * D_, D_);
            attn_mma_kernel<<<dim3(L_ / 64, H_, B_), 128,
                              6 * 64 * ATT_STR * sizeof(__nv_bfloat16)>>>();
            mma_gemm<1><<<dim3(D_ / 64, B_ * L_ / 128), 256>>>(
                (const float*)pATT, Wo, bo, (float*)pX, B_ * L_, D_, D_);
            ln_kernel<<<B_ * L_, 128>>>(out, (const float*)pX, ga, ba, out, 0);
        }
    }
}